// round 12
// baseline (speedup 1.0000x reference)
#include <cuda_runtime.h>
#include <cstdint>

// ---------------- problem constants ----------------
#define N_NODES 50000
#define N_PAD   50048          // multiple of 128
#define E_EDGES 800000
#define R_REL   8
#define B_BASES 8
#define H_DIM   128
#define L_LAYERS 3
#define FDIM    6
#define K_SUMS  1024           // R*H
#define K_TOT   1152           // R*H + H
#define BN_EPS  1e-5f
#define KCHUNK  32
#define NCHUNKS 36             // K_TOT / KCHUNK
#define SMPAD   36             // 32 + 4 pad floats per row
#define GEMM_SMEM ((4 * 128 * SMPAD + 1032) * 4)   // A/B stages + 1025 staged offsets

#define NR       (N_NODES * R_REL)        // 400000 segments
#define SCAN_EPB 1024
#define SCAN_NB  ((NR + SCAN_EPB - 1) / SCAN_EPB)   // 391

// ---------------- scratch (device globals) ----------------
__device__ float g_x[(size_t)N_PAD * H_DIM];     // residual stream (padding rows stay zero)
__device__ float g_WT[(size_t)H_DIM * K_TOT];    // fused weight, transposed [o][k], tf32-rounded
__device__ float g_h[(size_t)N_PAD * H_DIM];     // raw GEMM output (pre-BN; bias dropped)
__device__ int   g_cnt[NR];
__device__ int   g_off[NR + 1];
__device__ int   g_cursor[NR];
__device__ int   g_bsum[SCAN_NB];
__device__ int   g_esrc[E_EDGES];                // src ids sorted by (dst,rel)
__device__ float g_chs[H_DIM];
__device__ float g_chq[H_DIM];

// ---------------- helpers ----------------
__device__ __forceinline__ void cpa16(uint32_t dst, const void* src) {
    asm volatile("cp.async.cg.shared.global [%0], [%1], 16;" :: "r"(dst), "l"(src) : "memory");
}
__device__ __forceinline__ uint32_t smem_u32(const void* p) {
    uint32_t a;
    asm("{ .reg .u64 t; cvta.to.shared.u64 t, %1; cvt.u32.u64 %0, t; }" : "=r"(a) : "l"(p));
    return a;
}
__device__ __forceinline__ float round_tf32(float x) {
    float r;
    asm("cvt.rna.tf32.f32 %0, %1;" : "=f"(r) : "f"(x));
    return r;
}
__device__ __forceinline__ void mma_tf32(float& c0, float& c1, float& c2, float& c3,
                                         uint32_t a0, uint32_t a1, uint32_t a2, uint32_t a3,
                                         uint32_t b0, uint32_t b1) {
    asm volatile("mma.sync.aligned.m16n8k8.row.col.f32.tf32.tf32.f32 "
                 "{%0,%1,%2,%3}, {%4,%5,%6,%7}, {%8,%9}, {%0,%1,%2,%3};"
                 : "+f"(c0), "+f"(c1), "+f"(c2), "+f"(c3)
                 : "r"(a0), "r"(a1), "r"(a2), "r"(a3), "r"(b0), "r"(b1));
}
__device__ __forceinline__ void acc4(float4& a, const float4 v) {
    a.x += v.x; a.y += v.y; a.z += v.z; a.w += v.w;
}

// ---------------- setup: histogram + scan + bucket sort ----------------
__global__ void k_count(const int* __restrict__ ei, const int* __restrict__ et) {
    int e = blockIdx.x * blockDim.x + threadIdx.x;
    if (e < E_EDGES) atomicAdd(&g_cnt[ei[E_EDGES + e] * R_REL + et[e]], 1);
}
__global__ void k_scan1() {
    __shared__ int ts[256];
    int b = blockIdx.x, t = threadIdx.x;
    int base = b * SCAN_EPB + t * 4;
    int v0 = 0, v1 = 0, v2 = 0, v3 = 0;
    if (base + 4 <= NR) {
        int4 c = *reinterpret_cast<const int4*>(g_cnt + base);
        v0 = c.x; v1 = c.y; v2 = c.z; v3 = c.w;
    }
    int tsum = v0 + v1 + v2 + v3;
    ts[t] = tsum;
    __syncthreads();
#pragma unroll
    for (int o = 1; o < 256; o <<= 1) {
        int x = (t >= o) ? ts[t - o] : 0;
        __syncthreads();
        ts[t] += x;
        __syncthreads();
    }
    int texcl = ts[t] - tsum;
    if (base + 4 <= NR) {
        g_off[base + 0] = texcl;
        g_off[base + 1] = texcl + v0;
        g_off[base + 2] = texcl + v0 + v1;
        g_off[base + 3] = texcl + v0 + v1 + v2;
    }
    if (t == 255) g_bsum[b] = ts[255];
}
// fused: every block redundantly computes its exclusive block-prefix over g_bsum
__global__ void k_scan23() {
    __shared__ int red[256];
    int b = blockIdx.x, t = threadIdx.x;
    int part = 0;
    for (int i = t; i < b; i += 256) part += g_bsum[i];
    red[t] = part;
    __syncthreads();
#pragma unroll
    for (int o = 128; o > 0; o >>= 1) {
        if (t < o) red[t] += red[t + o];
        __syncthreads();
    }
    int add = red[0];
    int base = b * SCAN_EPB + t * 4;
#pragma unroll
    for (int j = 0; j < 4; j++) {
        int i = base + j;
        if (i < NR) {
            int v = g_off[i] + add;
            g_off[i] = v;
            g_cursor[i] = v;
        }
    }
    if (b == 0 && t == 0) g_off[NR] = E_EDGES;
}
__global__ void k_sortedge(const int* __restrict__ ei, const int* __restrict__ et) {
    int e = blockIdx.x * blockDim.x + threadIdx.x;
    if (e >= E_EDGES) return;
    int seg = ei[E_EDGES + e] * R_REL + et[e];
    int pos = atomicAdd(&g_cursor[seg], 1);
    g_esrc[pos] = ei[e];
}

// ---------------- init residual ----------------
__global__ void k_init(const int* __restrict__ xids, const float* __restrict__ nf,
                       const float* __restrict__ emb, const float* __restrict__ fw,
                       const float* __restrict__ fb, const float* __restrict__ vrt) {
    int n = blockIdx.x, h = threadIdx.x;
    __shared__ float f[FDIM];
    if (h < FDIM) f[h] = nf[n * FDIM + h];
    __syncthreads();
    float acc = fb[h];
#pragma unroll
    for (int d = 0; d < FDIM; d++) acc = fmaf(f[d], fw[h * FDIM + d], acc);
    g_x[(size_t)n * H_DIM + h] = emb[(size_t)xids[n] * H_DIM + h] + fmaxf(acc, 0.0f) + vrt[h];
}

// fused transposed weight WT[o][k], tf32-rounded; block (0,0) also zeroes BN accumulators
__global__ void k_weights(const float* __restrict__ bases, const float* __restrict__ comp,
                          const float* __restrict__ root, int l) {
    if (blockIdx.x == 0 && blockIdx.y == 0) {
        int t = threadIdx.x;
        if (t < H_DIM) { g_chs[t] = 0.0f; g_chq[t] = 0.0f; }
    }
    int k = blockIdx.x * blockDim.x + threadIdx.x;   // 0..1151
    int o = blockIdx.y;                              // 0..127
    float v;
    if (k < K_SUMS) {
        int r = k >> 7, i = k & 127;
        v = 0.0f;
        const float* cp = comp + (l * R_REL + r) * B_BASES;
#pragma unroll
        for (int b = 0; b < B_BASES; b++)
            v = fmaf(cp[b], bases[(((size_t)l * B_BASES + b) * H_DIM + i) * H_DIM + o], v);
    } else {
        v = root[((size_t)l * H_DIM + (k - K_SUMS)) * H_DIM + o];
    }
    g_WT[(size_t)o * K_TOT + k] = round_tf32(v);
}

// ---------------- fused gather+GEMM: g_h = [means(x,CSR) | x] @ WT^T ----------
// A-chunks built on the fly from CSR + g_x (no g_S intermediate at all).
__global__ __launch_bounds__(256, 2) void k_gemm() {
    extern __shared__ float sm[];
    float* As = sm;                          // [2][128][SMPAD]
    float* Bs = sm + 2 * 128 * SMPAD;        // [2][128][SMPAD]
    int*   offs = (int*)(sm + 4 * 128 * SMPAD);   // [1025]

    const int tid  = threadIdx.x;
    const int wid  = tid >> 5;
    const int lane = tid & 31;
    const int gID  = lane >> 2;
    const int tg   = lane & 3;
    const int wm   = wid & 1;
    const int wn   = wid >> 1;
    const int bm   = blockIdx.x * 128;

    const int lrow = tid >> 2;       // B loader: rows lrow, lrow+64
    const int lc4  = tid & 3;

    const int arow  = tid >> 1;      // A builder: row 0..127
    const int ahalf = (tid & 1) * 16;   // 16-col half within the 32-col chunk

    // stage CSR offsets for this CTA's 128 rows (1025 entries; pad rows -> empty)
    {
        int base_seg = bm * R_REL;
        for (int i = tid; i <= 1024; i += 256) {
            int idx = base_seg + i;
            offs[i] = (idx <= NR) ? g_off[idx] : E_EDGES;
        }
    }

    const float* bptr  = g_WT + (size_t)lrow * K_TOT;
    const float* bptr2 = bptr + (size_t)64 * K_TOT;
    uint32_t bs_base = smem_u32(Bs);

    float acc[4][4][4];
#pragma unroll
    for (int i = 0; i < 4; i++)
#pragma unroll
        for (int j = 0; j < 4; j++)
#pragma unroll
            for (int q = 0; q < 4; q++) acc[i][j][q] = 0.0f;

    auto loadB = [&](int t, int s) {
        uint32_t bd = bs_base + (uint32_t)(s * 128 * SMPAD) * 4;
        int ko = t * KCHUNK;
#pragma unroll
        for (int hh = 0; hh < 2; hh++) {
            int c = lc4 * 4 + hh * 16;
            cpa16(bd + (uint32_t)((lrow)      * SMPAD + c) * 4, bptr  + ko + c);
            cpa16(bd + (uint32_t)((lrow + 64) * SMPAD + c) * 4, bptr2 + ko + c);
        }
        asm volatile("cp.async.commit_group;" ::: "memory");
    };

    auto buildA = [&](int t, int s) {
        float* dst = As + s * 128 * SMPAD + arow * SMPAD + ahalf;
        if (t < 32) {
            int r = t >> 2, q = t & 3;
            int s0 = offs[arow * R_REL + r];
            int e0 = offs[arow * R_REL + r + 1];
            float4 a0 = make_float4(0,0,0,0), a1 = a0, a2 = a0, a3 = a0;
            int i = s0;
            // 2-wide unrolled: both indices first, then all 8 row loads in flight
            for (; i + 2 <= e0; i += 2) {
                int i0 = g_esrc[i], i1 = g_esrc[i + 1];
                const float* xp0 = g_x + (size_t)i0 * H_DIM + q * 32 + ahalf;
                const float* xp1 = g_x + (size_t)i1 * H_DIM + q * 32 + ahalf;
                float4 u0 = *reinterpret_cast<const float4*>(xp0 + 0);
                float4 u1 = *reinterpret_cast<const float4*>(xp0 + 4);
                float4 u2 = *reinterpret_cast<const float4*>(xp0 + 8);
                float4 u3 = *reinterpret_cast<const float4*>(xp0 + 12);
                float4 w0 = *reinterpret_cast<const float4*>(xp1 + 0);
                float4 w1 = *reinterpret_cast<const float4*>(xp1 + 4);
                float4 w2 = *reinterpret_cast<const float4*>(xp1 + 8);
                float4 w3 = *reinterpret_cast<const float4*>(xp1 + 12);
                acc4(a0, u0); acc4(a1, u1); acc4(a2, u2); acc4(a3, u3);
                acc4(a0, w0); acc4(a1, w1); acc4(a2, w2); acc4(a3, w3);
            }
            if (i < e0) {
                const float* xp = g_x + (size_t)g_esrc[i] * H_DIM + q * 32 + ahalf;
                acc4(a0, *reinterpret_cast<const float4*>(xp + 0));
                acc4(a1, *reinterpret_cast<const float4*>(xp + 4));
                acc4(a2, *reinterpret_cast<const float4*>(xp + 8));
                acc4(a3, *reinterpret_cast<const float4*>(xp + 12));
            }
            int c = e0 - s0;
            float inv = (c > 0) ? (1.0f / (float)c) : 0.0f;
            a0.x *= inv; a0.y *= inv; a0.z *= inv; a0.w *= inv;
            a1.x *= inv; a1.y *= inv; a1.z *= inv; a1.w *= inv;
            a2.x *= inv; a2.y *= inv; a2.z *= inv; a2.w *= inv;
            a3.x *= inv; a3.y *= inv; a3.z *= inv; a3.w *= inv;
            *reinterpret_cast<float4*>(dst + 0)  = a0;
            *reinterpret_cast<float4*>(dst + 4)  = a1;
            *reinterpret_cast<float4*>(dst + 8)  = a2;
            *reinterpret_cast<float4*>(dst + 12) = a3;
        } else {
            int q = t - 32;
            const float* xp = g_x + (size_t)(bm + arow) * H_DIM + q * 32 + ahalf;
            *reinterpret_cast<float4*>(dst + 0)  = *reinterpret_cast<const float4*>(xp + 0);
            *reinterpret_cast<float4*>(dst + 4)  = *reinterpret_cast<const float4*>(xp + 4);
            *reinterpret_cast<float4*>(dst + 8)  = *reinterpret_cast<const float4*>(xp + 8);
            *reinterpret_cast<float4*>(dst + 12) = *reinterpret_cast<const float4*>(xp + 12);
        }
    };

    loadB(0, 0);
    __syncthreads();            // offs visible
    buildA(0, 0);

    for (int t = 0; t < NCHUNKS; t++) {
        int s = t & 1;
        if (t + 1 < NCHUNKS) {
            loadB(t + 1, s ^ 1);
            asm volatile("cp.async.wait_group 1;" ::: "memory");
        } else {
            asm volatile("cp.async.wait_group 0;" ::: "memory");
        }
        __syncthreads();        // A(t) stores + B(t) visible

        const float* Asb = As + s * 128 * SMPAD;
        const float* Bsb = Bs + s * 128 * SMPAD;
#pragma unroll
        for (int ks = 0; ks < 4; ks++) {
            uint32_t bf[4][2];
#pragma unroll
            for (int nt = 0; nt < 4; nt++) {
                const float* bp = Bsb + (wn * 32 + nt * 8 + gID) * SMPAD + ks * 8 + tg;
                bf[nt][0] = __float_as_uint(bp[0]);
                bf[nt][1] = __float_as_uint(bp[4]);
            }
#pragma unroll
            for (int mt = 0; mt < 4; mt++) {
                const float* ap = Asb + (wm * 64 + mt * 16 + gID) * SMPAD + ks * 8 + tg;
                uint32_t a0 = __float_as_uint(ap[0]);
                uint32_t a1 = __float_as_uint(ap[8 * SMPAD]);
                uint32_t a2 = __float_as_uint(ap[4]);
                uint32_t a3 = __float_as_uint(ap[8 * SMPAD + 4]);
#pragma unroll
                for (int nt = 0; nt < 4; nt++)
                    mma_tf32(acc[mt][nt][0], acc[mt][nt][1], acc[mt][nt][2], acc[mt][nt][3],
                             a0, a1, a2, a3, bf[nt][0], bf[nt][1]);
            }
        }
        if (t + 1 < NCHUNKS) buildA(t + 1, s ^ 1);   // overlaps: LDG latency runs into next sync
        __syncthreads();        // stage s free for t+2; build stores ordered for t+1
    }

    // epilogue: store h + fused BN column stats
    float colS[4][2], colQ[4][2];
#pragma unroll
    for (int nt = 0; nt < 4; nt++)
#pragma unroll
        for (int j = 0; j < 2; j++) { colS[nt][j] = 0.0f; colQ[nt][j] = 0.0f; }

#pragma unroll
    for (int mt = 0; mt < 4; mt++) {
        int row0 = bm + wm * 64 + mt * 16 + gID;
        int row1 = row0 + 8;
#pragma unroll
        for (int nt = 0; nt < 4; nt++) {
            int col = wn * 32 + nt * 8 + tg * 2;
            float c0 = acc[mt][nt][0], c1 = acc[mt][nt][1];
            float c2 = acc[mt][nt][2], c3 = acc[mt][nt][3];
            *reinterpret_cast<float2*>(g_h + (size_t)row0 * H_DIM + col) = make_float2(c0, c1);
            *reinterpret_cast<float2*>(g_h + (size_t)row1 * H_DIM + col) = make_float2(c2, c3);
            if (row0 < N_NODES) {
                colS[nt][0] += c0; colQ[nt][0] += c0 * c0;
                colS[nt][1] += c1; colQ[nt][1] += c1 * c1;
            }
            if (row1 < N_NODES) {
                colS[nt][0] += c2; colQ[nt][0] += c2 * c2;
                colS[nt][1] += c3; colQ[nt][1] += c3 * c3;
            }
        }
    }
    __syncthreads();
    float* bns = sm;
    float* bnq = sm + 128;
    if (tid < 128) { bns[tid] = 0.0f; bnq[tid] = 0.0f; }
    __syncthreads();
#pragma unroll
    for (int nt = 0; nt < 4; nt++)
#pragma unroll
        for (int j = 0; j < 2; j++) {
            int col = wn * 32 + nt * 8 + tg * 2 + j;
            atomicAdd(&bns[col], colS[nt][j]);
            atomicAdd(&bnq[col], colQ[nt][j]);
        }
    __syncthreads();
    if (tid < 128) {
        atomicAdd(&g_chs[tid], bns[tid]);
        atomicAdd(&g_chq[tid], bnq[tid]);
    }
}

// ---------------- BN finalize + residual update ----------------
__global__ void k_bnstats() {
    int c = threadIdx.x;
    float mu  = g_chs[c] * (1.0f / N_NODES);
    float var = g_chq[c] * (1.0f / N_NODES) - mu * mu;
    g_chs[c] = mu;
    g_chq[c] = rsqrtf(var + BN_EPS);
}
__global__ void k_update(const float* __restrict__ gamma, const float* __restrict__ beta,
                         int l, float* __restrict__ out, int last) {
    int n = blockIdx.x, h = threadIdx.x;
    float v  = g_h[(size_t)n * H_DIM + h];
    float hn = gamma[l * H_DIM + h] * (v - g_chs[h]) * g_chq[h] + beta[l * H_DIM + h];
    float* xp = g_x + (size_t)n * H_DIM + h;
    float nx = *xp + fmaxf(hn, 0.0f);
    *xp = nx;
    if (last) out[(size_t)n * H_DIM + h] = nx;
}

// ---------------- launch ----------------
extern "C" void kernel_launch(void* const* d_in, const int* in_sizes, int n_in,
                              void* d_out, int out_size) {
    const int*   x_ids = (const int*)  d_in[0];
    const int*   eidx  = (const int*)  d_in[1];
    const int*   etype = (const int*)  d_in[2];
    const float* nf    = (const float*)d_in[3];
    const float* emb   = (const float*)d_in[4];
    const float* fw    = (const float*)d_in[5];
    const float* fb    = (const float*)d_in[6];
    const float* vrt   = (const float*)d_in[7];
    const float* bases = (const float*)d_in[8];
    const float* comp  = (const float*)d_in[9];
    const float* root  = (const float*)d_in[10];
    const float* gamma = (const float*)d_in[12];
    const float* beta  = (const float*)d_in[13];
    float* out = (float*)d_out;

    cudaFuncSetAttribute(k_gemm, cudaFuncAttributeMaxDynamicSharedMemorySize, GEMM_SMEM);

    void* p_cnt;
    cudaGetSymbolAddress(&p_cnt, g_cnt);

    // one-time topology setup: histogram -> scan -> bucket sort
    cudaMemsetAsync(p_cnt, 0, sizeof(int) * NR, 0);
    k_count<<<(E_EDGES + 255) / 256, 256>>>(eidx, etype);
    k_scan1<<<SCAN_NB, 256>>>();
    k_scan23<<<SCAN_NB, 256>>>();
    k_sortedge<<<(E_EDGES + 255) / 256, 256>>>(eidx, etype);
    k_init<<<N_NODES, H_DIM>>>(x_ids, nf, emb, fw, fb, vrt);

    for (int l = 0; l < L_LAYERS; l++) {
        k_weights<<<dim3(9, 128), 128>>>(bases, comp, root, l);
        k_gemm<<<N_PAD / 128, 256, GEMM_SMEM>>>();
        k_bnstats<<<1, H_DIM>>>();
        k_update<<<N_NODES, H_DIM>>>(gamma, beta, l, out, l == L_LAYERS - 1);
    }
}